// round 16
// baseline (speedup 1.0000x reference)
#include <cuda_runtime.h>
#include <cstdint>
#include <cstring>

#define Bx 64
#define Cx 3
#define Hx 384
#define Wx 384
#define PLANE (Hx * Wx)          // 147456
#define IMGS_PER_TEX 16
#define TEX_H (IMGS_PER_TEX * Cx * Hx)   // 18432 rows

// Dual-stream kernel: every thread carries TWO independent pixel streams,
// one on the TEX pipe (rows ys..ys+3) and one on the LSU pipe (rows
// ys+4..ys+7) of the SAME image. Independent coordinate/weight/FMA chains
// per stream -> each pipe's latency is hidden by the other's work.
__global__ __launch_bounds__(256) void affine_dual_kernel(
    cudaTextureObject_t t0, cudaTextureObject_t t1,
    cudaTextureObject_t t2, cudaTextureObject_t t3,
    const float* __restrict__ imgs,
    const float* __restrict__ theta,
    float* __restrict__ out,
    int tex_ok)
{
    int lane  = threadIdx.x;          // 0..31
    int w     = threadIdx.y;          // 0..7
    int warpx = w & 3;
    int warpy = w >> 2;

    int x    = blockIdx.x * 128 + warpx * 32 + lane;
    int ys   = blockIdx.y * 16 + warpy * 8;   // this warp's 8-row strip
    int b    = blockIdx.z;

    const float* th = theta + b * 6;
    float t00 = __ldg(th + 0), t01 = __ldg(th + 1), t02 = __ldg(th + 2);
    float t10 = __ldg(th + 3), t11 = __ldg(th + 4), t12 = __ldg(th + 5);

    cudaTextureObject_t tex = (b & 32) ? ((b & 16) ? t3 : t2)
                                       : ((b & 16) ? t1 : t0);
    float rowb = (float)((b & (IMGS_PER_TEX - 1)) * Cx * Hx);

    float xv  = (float)x - 191.5f;
    float ixx = fmaf(xv, t00, t02 + 191.5f);
    float iyx = fmaf(xv, t10, t12 + 191.5f);

    const float* img  = imgs + (size_t)b * (Cx * PLANE);
    float*       outb = out  + (size_t)b * (Cx * PLANE);

    if (tex_ok) {
#pragma unroll
        for (int r = 0; r < 4; r++) {
            // ======== stream T: TEX pipe, row ys + r ========
            int yT = ys + r;
            float yvT = (float)yT - 191.5f;
            float ixT = fmaf(yvT, t01, ixx);
            float iyT = fmaf(yvT, t11, iyx);
            float fxT = floorf(ixT), fyT = floorf(iyT);

            float gx = fxT + 1.0f;
            float gy = rowb + fyT + 1.0f;
            float4 g0 = tex2Dgather<float4>(tex, gx, gy, 0);
            float4 g1 = tex2Dgather<float4>(tex, gx, gy + (float)Hx, 0);
            float4 g2 = tex2Dgather<float4>(tex, gx, gy + (float)(2 * Hx), 0);

            // ======== stream L: LSU pipe, row ys + 4 + r ========
            int yL = ys + 4 + r;
            float yvL = (float)yL - 191.5f;
            float ixL = fmaf(yvL, t01, ixx);
            float iyL = fmaf(yvL, t11, iyx);
            float fxL = floorf(ixL), fyL = floorf(iyL);

            int x0L = (int)fxL, y0L = (int)fyL;
            int x1L = x0L + 1,  y1L = y0L + 1;

            int xc0 = min(max(x0L, 0), Wx - 1);
            int xc1 = min(max(x1L, 0), Wx - 1);
            int yc0 = min(max(y0L, 0), Hx - 1);
            int yc1 = min(max(y1L, 0), Hx - 1);

            int o00 = yc0 * Wx + xc0;
            int o10 = yc0 * Wx + xc1;
            int o01 = yc1 * Wx + xc0;
            int o11 = yc1 * Wx + xc1;

            float A0 = __ldg(img + o00);
            float B0 = __ldg(img + o10);
            float C0 = __ldg(img + o01);
            float D0 = __ldg(img + o11);
            float A1 = __ldg(img + PLANE + o00);
            float B1 = __ldg(img + PLANE + o10);
            float C1 = __ldg(img + PLANE + o01);
            float D1 = __ldg(img + PLANE + o11);
            float A2 = __ldg(img + 2 * PLANE + o00);
            float B2 = __ldg(img + 2 * PLANE + o10);
            float C2 = __ldg(img + 2 * PLANE + o01);
            float D2 = __ldg(img + 2 * PLANE + o11);

            // ---- weights T (y-validity folded; x handled by HW border) ----
            float wx1T = ixT - fxT, wy1T = iyT - fyT;
            float wx0T = 1.0f - wx1T, wy0T = 1.0f - wy1T;
            int y0T = (int)fyT, y1T = y0T + 1;
            float vty0 = (y0T >= 0 && y0T < Hx) ? wy0T : 0.0f;
            float vty1 = (y1T >= 0 && y1T < Hx) ? wy1T : 0.0f;
            float wT00 = wx0T * vty0, wT10 = wx1T * vty0;
            float wT01 = wx0T * vty1, wT11 = wx1T * vty1;

            // ---- weights L (full validity folded) ----
            float wx1L = ixL - fxL, wy1L = iyL - fyL;
            float wx0L = 1.0f - wx1L, wy0L = 1.0f - wy1L;
            float vx0 = (x0L >= 0 && x0L < Wx) ? 1.0f : 0.0f;
            float vx1 = (x1L >= 0 && x1L < Wx) ? 1.0f : 0.0f;
            float vy0 = (y0L >= 0 && y0L < Hx) ? 1.0f : 0.0f;
            float vy1 = (y1L >= 0 && y1L < Hx) ? 1.0f : 0.0f;
            float wL00 = wx0L * wy0L * vx0 * vy0;
            float wL10 = wx1L * wy0L * vx1 * vy0;
            float wL01 = wx0L * wy1L * vx0 * vy1;
            float wL11 = wx1L * wy1L * vx1 * vy1;

            // ---- consume stream T (gather order: .w .z .x .y) ----
            float rT0 = fmaf(wT00, g0.w, fmaf(wT10, g0.z, fmaf(wT01, g0.x, wT11 * g0.y)));
            float rT1 = fmaf(wT00, g1.w, fmaf(wT10, g1.z, fmaf(wT01, g1.x, wT11 * g1.y)));
            float rT2 = fmaf(wT00, g2.w, fmaf(wT10, g2.z, fmaf(wT01, g2.x, wT11 * g2.y)));

            // ---- consume stream L ----
            float rL0 = fmaf(wL00, A0, fmaf(wL10, B0, fmaf(wL01, C0, wL11 * D0)));
            float rL1 = fmaf(wL00, A1, fmaf(wL10, B1, fmaf(wL01, C1, wL11 * D1)));
            float rL2 = fmaf(wL00, A2, fmaf(wL10, B2, fmaf(wL01, C2, wL11 * D2)));

            int offT = yT * Wx + x;
            int offL = yL * Wx + x;
            outb[0 * PLANE + offT] = rT0;
            outb[1 * PLANE + offT] = rT1;
            outb[2 * PLANE + offT] = rT2;
            outb[0 * PLANE + offL] = rL0;
            outb[1 * PLANE + offL] = rL1;
            outb[2 * PLANE + offL] = rL2;
        }
    } else {
        // fallback: all 8 rows via proven LDG path
#pragma unroll
        for (int r = 0; r < 8; r++) {
            int y = ys + r;
            float yv = (float)y - 191.5f;
            float ix = fmaf(yv, t01, ixx);
            float iy = fmaf(yv, t11, iyx);

            float fx0 = floorf(ix), fy0 = floorf(iy);
            float wx1 = ix - fx0,  wy1 = iy - fy0;
            float wx0 = 1.0f - wx1, wy0 = 1.0f - wy1;

            int x0 = (int)fx0, y0 = (int)fy0;
            int x1 = x0 + 1,  y1 = y0 + 1;

            float vx0 = (x0 >= 0 && x0 < Wx) ? 1.0f : 0.0f;
            float vx1 = (x1 >= 0 && x1 < Wx) ? 1.0f : 0.0f;
            float vy0 = (y0 >= 0 && y0 < Hx) ? 1.0f : 0.0f;
            float vy1 = (y1 >= 0 && y1 < Hx) ? 1.0f : 0.0f;

            float w00 = wx0 * wy0 * vx0 * vy0;
            float w10 = wx1 * wy0 * vx1 * vy0;
            float w01 = wx0 * wy1 * vx0 * vy1;
            float w11 = wx1 * wy1 * vx1 * vy1;

            int xc0 = min(max(x0, 0), Wx - 1);
            int xc1 = min(max(x1, 0), Wx - 1);
            int yc0 = min(max(y0, 0), Hx - 1);
            int yc1 = min(max(y1, 0), Hx - 1);

            int o00 = yc0 * Wx + xc0;
            int o10 = yc0 * Wx + xc1;
            int o01 = yc1 * Wx + xc0;
            int o11 = yc1 * Wx + xc1;

            float r0 = fmaf(w00, __ldg(img + o00), fmaf(w10, __ldg(img + o10),
                       fmaf(w01, __ldg(img + o01), w11 * __ldg(img + o11))));
            float r1 = fmaf(w00, __ldg(img + PLANE + o00), fmaf(w10, __ldg(img + PLANE + o10),
                       fmaf(w01, __ldg(img + PLANE + o01), w11 * __ldg(img + PLANE + o11))));
            float r2 = fmaf(w00, __ldg(img + 2*PLANE + o00), fmaf(w10, __ldg(img + 2*PLANE + o10),
                       fmaf(w01, __ldg(img + 2*PLANE + o01), w11 * __ldg(img + 2*PLANE + o11))));

            int rowoff = y * Wx + x;
            outb[0 * PLANE + rowoff] = r0;
            outb[1 * PLANE + rowoff] = r1;
            outb[2 * PLANE + rowoff] = r2;
        }
    }
}

extern "C" void kernel_launch(void* const* d_in, const int* in_sizes, int n_in,
                              void* d_out, int out_size)
{
    const float* imgs  = (const float*)d_in[0];
    const float* theta = (const float*)d_in[1];
    float* out = (float*)d_out;

    // One-time texture-object setup OUTSIDE graph capture (proven pattern).
    static cudaTextureObject_t tex[4] = {0, 0, 0, 0};
    static const float* cached_imgs = nullptr;
    static int tex_ok = 0;

    if (cached_imgs != imgs) {
        cudaStreamCaptureStatus cs = cudaStreamCaptureStatusNone;
        cudaStreamIsCapturing(cudaStreamLegacy, &cs);
        if (cs == cudaStreamCaptureStatusNone) {
            int ok = 1;
            for (int g = 0; g < 4 && ok; g++) {
                cudaResourceDesc rd;
                memset(&rd, 0, sizeof(rd));
                rd.resType = cudaResourceTypePitch2D;
                rd.res.pitch2D.devPtr =
                    (void*)(imgs + (size_t)g * IMGS_PER_TEX * Cx * PLANE);
                rd.res.pitch2D.desc = cudaCreateChannelDesc<float>();
                rd.res.pitch2D.width = Wx;
                rd.res.pitch2D.height = TEX_H;
                rd.res.pitch2D.pitchInBytes = Wx * sizeof(float);

                cudaTextureDesc td;
                memset(&td, 0, sizeof(td));
                td.addressMode[0] = cudaAddressModeBorder;  // OOB -> 0
                td.addressMode[1] = cudaAddressModeBorder;
                td.filterMode = cudaFilterModePoint;
                td.readMode = cudaReadModeElementType;
                td.normalizedCoords = 0;

                if (cudaCreateTextureObject(&tex[g], &rd, &td, nullptr)
                    != cudaSuccess) ok = 0;
            }
            tex_ok = ok;
            cached_imgs = imgs;
        }
    }

    int use_tex = (tex_ok && cached_imgs == imgs) ? 1 : 0;

    dim3 block(32, 8);
    dim3 grid(Wx / 128, Hx / 16, Bx);   // (3, 24, 64) = 4608 blocks
    affine_dual_kernel<<<grid, block>>>(tex[0], tex[1], tex[2], tex[3],
                                        imgs, theta, out, use_tex);
}